// round 3
// baseline (speedup 1.0000x reference)
#include <cuda_runtime.h>

#define B_    4
#define T_    2048
#define DI    512
#define DO    512
#define NF    24
#define KDIM  (NF * DI)      // 12288
#define MROWS (B_ * T_)      // 8192

// Scratch: A[(b*T+t)][(n*DI+f)] = phi[t,n] * cumsum_t(phi[t,n]*x[b,t,f])  (402 MB)
static __device__ float g_A[(size_t)MROWS * KDIM];
// W[(n*DI+f)][o] = M_weights[n][o][f]  (25 MB)
static __device__ float g_W[(size_t)KDIM * DO];

// ---------------------------------------------------------------------------
// Kernel 0: transpose M_weights (n,o,f) -> W[(n,f),o]
// ---------------------------------------------------------------------------
__global__ void transpose_w_kernel(const float* __restrict__ Mw) {
    __shared__ float tile[32][33];
    const int n  = blockIdx.z;
    const int f0 = blockIdx.x * 32;
    const int o0 = blockIdx.y * 32;
    const int tx = threadIdx.x;   // 0..31
    const int ty = threadIdx.y;   // 0..7
#pragma unroll
    for (int i = 0; i < 32; i += 8)
        tile[ty + i][tx] = Mw[((size_t)n * DO + (o0 + ty + i)) * DI + (f0 + tx)];
    __syncthreads();
#pragma unroll
    for (int i = 0; i < 32; i += 8)
        g_W[((size_t)n * DI + (f0 + ty + i)) * DO + (o0 + tx)] = tile[tx][ty + i];
}

// ---------------------------------------------------------------------------
// Kernel 1: weighted causal scan producing A
// grid (NF, B, DI/128), block 128. One thread owns one (b,n,f) chain.
// Unroll-8 load batching -> MLP=8 hides memory latency of the serial scan.
// ---------------------------------------------------------------------------
__global__ void scan_kernel(const float* __restrict__ x,
                            const float* __restrict__ filt) {
    __shared__ float ph[T_];
    const int n = blockIdx.x;
    const int b = blockIdx.y;
    const int f = blockIdx.z * 128 + threadIdx.x;

    for (int t = threadIdx.x; t < T_; t += 128)
        ph[t] = filt[t * NF + n];
    __syncthreads();

    const float* xb = x   + (size_t)b * T_ * DI   + f;
    float*       Ab = g_A + (size_t)b * T_ * KDIM + n * DI + f;

    float s = 0.f;
    for (int t0 = 0; t0 < T_; t0 += 8) {
        float xv[8];
#pragma unroll
        for (int u = 0; u < 8; u++)
            xv[u] = xb[(size_t)(t0 + u) * DI];
#pragma unroll
        for (int u = 0; u < 8; u++) {
            const float p = ph[t0 + u];
            s = fmaf(p, xv[u], s);
            Ab[(size_t)(t0 + u) * KDIM] = p * s;
        }
    }
}

// ---------------------------------------------------------------------------
// Kernel 2: C[8192,512] = A[8192,12288] @ W[12288,512], fp32 SIMT
// 128x128x16 block tile, 8x8 per thread, 256 threads, register prefetch.
// ---------------------------------------------------------------------------
__global__ __launch_bounds__(256, 2) void gemm_kernel(float* __restrict__ C) {
    __shared__ float As[16][136];   // +8 pad: conflict-free transpose store
    __shared__ float Bs[16][132];

    const int tid  = threadIdx.x;
    const int brow = blockIdx.y;
    const int bcol = blockIdx.x;

    const float* Ag = g_A + (size_t)brow * 128 * KDIM;
    const float* Bg = g_W + bcol * 128;

    float acc[8][8];
#pragma unroll
    for (int i = 0; i < 8; i++)
#pragma unroll
        for (int j = 0; j < 8; j++) acc[i][j] = 0.f;

    const int aRow = tid >> 2;           // 0..63
    const int aCol = (tid & 3) * 4;      // 0,4,8,12
    const int bRow = tid >> 5;           // 0..7
    const int bCol = (tid & 31) * 4;     // 0..124
    const int tx   = tid & 15;
    const int ty   = tid >> 4;

    // initial tile load (k0 = 0)
    {
#pragma unroll
        for (int r = 0; r < 128; r += 64) {
            float4 v = *(const float4*)(Ag + (size_t)(aRow + r) * KDIM + aCol);
            As[aCol + 0][aRow + r] = v.x;
            As[aCol + 1][aRow + r] = v.y;
            As[aCol + 2][aRow + r] = v.z;
            As[aCol + 3][aRow + r] = v.w;
        }
#pragma unroll
        for (int r = 0; r < 16; r += 8)
            *(float4*)(&Bs[bRow + r][bCol]) =
                *(const float4*)(Bg + (size_t)(bRow + r) * DO + bCol);
    }
    __syncthreads();

    for (int k0 = 0; k0 < KDIM; k0 += 16) {
        float4 va0, va1, vb0, vb1;
        const bool has_next = (k0 + 16 < KDIM);
        if (has_next) {
            const int kn = k0 + 16;
            va0 = *(const float4*)(Ag + (size_t)(aRow     ) * KDIM + kn + aCol);
            va1 = *(const float4*)(Ag + (size_t)(aRow + 64) * KDIM + kn + aCol);
            vb0 = *(const float4*)(Bg + (size_t)(kn + bRow    ) * DO + bCol);
            vb1 = *(const float4*)(Bg + (size_t)(kn + bRow + 8) * DO + bCol);
        }

#pragma unroll
        for (int kk = 0; kk < 16; kk++) {
            float rm[8], rn[8];
#pragma unroll
            for (int i = 0; i < 8; i++) rm[i] = As[kk][ty * 8 + i];
#pragma unroll
            for (int j = 0; j < 8; j++) rn[j] = Bs[kk][tx * 8 + j];
#pragma unroll
            for (int i = 0; i < 8; i++)
#pragma unroll
                for (int j = 0; j < 8; j++)
                    acc[i][j] = fmaf(rm[i], rn[j], acc[i][j]);
        }
        __syncthreads();

        if (has_next) {
            As[aCol + 0][aRow]      = va0.x;
            As[aCol + 1][aRow]      = va0.y;
            As[aCol + 2][aRow]      = va0.z;
            As[aCol + 3][aRow]      = va0.w;
            As[aCol + 0][aRow + 64] = va1.x;
            As[aCol + 1][aRow + 64] = va1.y;
            As[aCol + 2][aRow + 64] = va1.z;
            As[aCol + 3][aRow + 64] = va1.w;
            *(float4*)(&Bs[bRow    ][bCol]) = vb0;
            *(float4*)(&Bs[bRow + 8][bCol]) = vb1;
            __syncthreads();
        }
    }

#pragma unroll
    for (int i = 0; i < 8; i++) {
        const int row = brow * 128 + ty * 8 + i;
        float* Crow = C + (size_t)row * DO + bcol * 128 + tx * 8;
#pragma unroll
        for (int j = 0; j < 8; j += 4) {
            float4 v = make_float4(acc[i][j], acc[i][j + 1],
                                   acc[i][j + 2], acc[i][j + 3]);
            *(float4*)(Crow + j) = v;
        }
    }
}

// ---------------------------------------------------------------------------
extern "C" void kernel_launch(void* const* d_in, const int* in_sizes, int n_in,
                              void* d_out, int out_size) {
    (void)in_sizes; (void)n_in; (void)out_size;
    const float* x    = (const float*)d_in[0];   // (B, T, DI)
    const float* filt = (const float*)d_in[1];   // (T, NF)
    const float* Mw   = (const float*)d_in[2];   // (NF, DO, DI)
    float*       out  = (float*)d_out;           // (B, T, DO)

    transpose_w_kernel<<<dim3(DI / 32, DO / 32, NF), dim3(32, 8)>>>(Mw);
    scan_kernel<<<dim3(NF, B_, DI / 128), 128>>>(x, filt);
    gemm_kernel<<<dim3(DO / 128, MROWS / 128), 256>>>(out);
}

// round 7
// speedup vs baseline: 2.1017x; 2.1017x over previous
#include <cuda_runtime.h>
#include <cuda_bf16.h>
#include <cstdint>

#define B_    4
#define T_    2048
#define DI    512
#define DO    512
#define NF    24
#define KDIM  (NF * DI)      // 12288
#define MROWS (B_ * T_)      // 8192

#define BM 128
#define BN 128
#define BK 64
#define NCHUNK (KDIM / BK)   // 192
#define STAGE_BYTES 65536    // Ahi 16K + Alo 16K + Bhi 16K + Blo 16K
#define NSTAGE 3
#define SMEM_TOTAL (NSTAGE * STAGE_BYTES + 1024)

// bf16 hi/lo split operands
static __device__ __nv_bfloat16 g_Ahi[(size_t)MROWS * KDIM];
static __device__ __nv_bfloat16 g_Alo[(size_t)MROWS * KDIM];
static __device__ __nv_bfloat16 g_Whi[(size_t)DO * KDIM];   // [o][n*DI+f]  (col-major B)
static __device__ __nv_bfloat16 g_Wlo[(size_t)DO * KDIM];

// ---------------------------------------------------------------------------
// helpers (all base sm_80/90 PTX — NO tcgen05: harness assembles for sm_103
// without the 'a' feature set, which rejects tcgen05/TMEM instructions)
// ---------------------------------------------------------------------------
__device__ __forceinline__ uint32_t smem_u32(const void* p) {
    uint32_t a;
    asm("{ .reg .u64 t; cvta.to.shared.u64 t, %1; cvt.u32.u64 %0, t; }"
        : "=r"(a) : "l"(p));
    return a;
}
__device__ __forceinline__ void cp16(uint32_t s, const void* g) {
    asm volatile("cp.async.cg.shared.global [%0], [%1], 16;\n"
                 :: "r"(s), "l"(g) : "memory");
}
#define CP_COMMIT() asm volatile("cp.async.commit_group;\n" ::: "memory")
#define CP_WAIT1()  asm volatile("cp.async.wait_group 1;\n" ::: "memory")
#define CP_WAIT0()  asm volatile("cp.async.wait_group 0;\n" ::: "memory")
#define SWZ(x) ((x) ^ (((x) >> 3) & 0x70))

// ldmatrix x4, non-transposed. Source rows are 16B; addr per lane.
__device__ __forceinline__ void ldsm4(uint32_t* r, uint32_t addr) {
    asm volatile("ldmatrix.sync.aligned.m8n8.x4.shared.b16 {%0,%1,%2,%3}, [%4];"
                 : "=r"(r[0]), "=r"(r[1]), "=r"(r[2]), "=r"(r[3]) : "r"(addr));
}
// mma m16n8k16 row.col bf16 -> fp32, acc in place
__device__ __forceinline__ void mma16816(float* d, const uint32_t* a,
                                         uint32_t b0, uint32_t b1) {
    asm volatile(
        "mma.sync.aligned.m16n8k16.row.col.f32.bf16.bf16.f32 "
        "{%0,%1,%2,%3}, {%4,%5,%6,%7}, {%8,%9}, {%0,%1,%2,%3};"
        : "+f"(d[0]), "+f"(d[1]), "+f"(d[2]), "+f"(d[3])
        : "r"(a[0]), "r"(a[1]), "r"(a[2]), "r"(a[3]), "r"(b0), "r"(b1));
}

// ---------------------------------------------------------------------------
// Kernel 0: convert M_weights (n,o,f) fp32 -> W_hi/W_lo bf16 [o][n*DI+f]
// ---------------------------------------------------------------------------
__global__ void convert_w_kernel(const float* __restrict__ Mw) {
    size_t i = (size_t)blockIdx.x * 256 + threadIdx.x;   // over NF*DO*DI
    int f = (int)(i & (DI - 1));
    int o = (int)((i >> 9) & (DO - 1));
    int n = (int)(i >> 18);
    float v = Mw[i];
    __nv_bfloat16 hi = __float2bfloat16(v);
    float lo = v - __bfloat162float(hi);
    size_t d = (size_t)o * KDIM + (size_t)n * DI + f;
    g_Whi[d] = hi;
    g_Wlo[d] = __float2bfloat16(lo);
}

// ---------------------------------------------------------------------------
// Kernel 1: weighted causal scan -> A_hi/A_lo bf16 [(b*T+t)][n*DI+f]
// ---------------------------------------------------------------------------
__global__ void scan_kernel(const float* __restrict__ x,
                            const float* __restrict__ filt) {
    __shared__ float ph[T_];
    const int n = blockIdx.x;
    const int b = blockIdx.y;
    const int f = blockIdx.z * 128 + threadIdx.x;

    for (int t = threadIdx.x; t < T_; t += 128)
        ph[t] = filt[t * NF + n];
    __syncthreads();

    const float* xb = x + (size_t)b * T_ * DI + f;
    const size_t base = (size_t)b * T_ * KDIM + (size_t)n * DI + f;

    float s = 0.f;
    for (int t0 = 0; t0 < T_; t0 += 8) {
        float xv[8];
#pragma unroll
        for (int u = 0; u < 8; u++)
            xv[u] = xb[(size_t)(t0 + u) * DI];
#pragma unroll
        for (int u = 0; u < 8; u++) {
            const float p = ph[t0 + u];
            s = fmaf(p, xv[u], s);
            const float v = p * s;
            const __nv_bfloat16 hi = __float2bfloat16(v);
            const float lo = v - __bfloat162float(hi);
            const size_t idx = base + (size_t)(t0 + u) * KDIM;
            g_Ahi[idx] = hi;
            g_Alo[idx] = __float2bfloat16(lo);
        }
    }
}

// ---------------------------------------------------------------------------
// Kernel 2: split-bf16 GEMM via mma.sync, CTA 128x128, BK=64, 3-stage cp.async
// ---------------------------------------------------------------------------
__device__ __forceinline__ void load_chunk(uint32_t tiles, int stage,
                                           const __nv_bfloat16* Ah,
                                           const __nv_bfloat16* Al,
                                           const __nv_bfloat16* Bh,
                                           const __nv_bfloat16* Bl,
                                           int k0, int tid) {
    const uint32_t s = tiles + stage * STAGE_BYTES;
    const __nv_bfloat16* ah = Ah + k0;
    const __nv_bfloat16* al = Al + k0;
    const __nv_bfloat16* bh = Bh + k0;
    const __nv_bfloat16* bl = Bl + k0;
    // each subtile: 128 rows x 128B = 1024 x 16B units
#pragma unroll
    for (int j = 0; j < 4; j++) {
        const int u = j * 256 + tid;
        const int r = u >> 3, seg = u & 7;
        const uint32_t so = SWZ((uint32_t)(r * 128 + seg * 16));
        const size_t go = (size_t)r * KDIM + seg * 8;
        cp16(s +         so, ah + go);
        cp16(s + 16384 + so, al + go);
        cp16(s + 32768 + so, bh + go);
        cp16(s + 49152 + so, bl + go);
    }
    CP_COMMIT();
}

__global__ __launch_bounds__(256, 1) void gemm_kernel(float* __restrict__ C) {
    extern __shared__ char smem[];
    const uint32_t sb    = smem_u32(smem);
    const uint32_t tiles = (sb + 1023) & ~1023u;   // 128B-swizzle-friendly base

    const int tid  = threadIdx.x;
    const int wid  = tid >> 5;
    const int lane = tid & 31;
    const int m0 = blockIdx.y * BM;
    const int n0 = blockIdx.x * BN;
    const int wm = (wid >> 2) * 64;     // warp m-offset (0 or 64)
    const int wn = (wid & 3) * 32;      // warp n-offset (0,32,64,96)
    const int lr = lane & 15;           // ldmatrix row-in-tile
    const int lc = lane >> 4;           // ldmatrix k-half (0/1)

    const __nv_bfloat16* Ah = g_Ahi + (size_t)m0 * KDIM;
    const __nv_bfloat16* Al = g_Alo + (size_t)m0 * KDIM;
    const __nv_bfloat16* Bh = g_Whi + (size_t)n0 * KDIM;
    const __nv_bfloat16* Bl = g_Wlo + (size_t)n0 * KDIM;

    float acc[4][4][4];                 // [m-tile][n8-tile][frag]
#pragma unroll
    for (int i = 0; i < 4; i++)
#pragma unroll
        for (int j = 0; j < 4; j++)
#pragma unroll
            for (int r = 0; r < 4; r++) acc[i][j][r] = 0.f;

    load_chunk(tiles, 0, Ah, Al, Bh, Bl, 0, tid);
    load_chunk(tiles, 1, Ah, Al, Bh, Bl, BK, tid);

    for (int ch = 0; ch < NCHUNK; ch++) {
        if (ch == NCHUNK - 1) { CP_WAIT0(); } else { CP_WAIT1(); }
        __syncthreads();

        const uint32_t base = tiles + (ch % NSTAGE) * STAGE_BYTES;
#pragma unroll
        for (int ks = 0; ks < 4; ks++) {
            uint32_t aH[16], aL[16], bH[8], bL[8];
            const uint32_t kb = (uint32_t)(ks * 32 + lc * 16);
#pragma unroll
            for (int i = 0; i < 4; i++) {
                const uint32_t off = SWZ((uint32_t)((wm + i * 16 + lr) * 128) + kb);
                ldsm4(aH + 4 * i, base +         off);
                ldsm4(aL + 4 * i, base + 16384 + off);
            }
#pragma unroll
            for (int j = 0; j < 2; j++) {
                const uint32_t off = SWZ((uint32_t)((wn + j * 16 + lr) * 128) + kb);
                ldsm4(bH + 4 * j, base + 32768 + off);
                ldsm4(bL + 4 * j, base + 49152 + off);
            }
            // 3 split passes: hi*hi, hi*lo, lo*hi (lo*lo dropped, ~2^-18)
#pragma unroll
            for (int i = 0; i < 4; i++) {
#pragma unroll
                for (int j = 0; j < 2; j++) {
                    // x4 ldmatrix result: r0=(rows0-7,k0-7), r1=(rows8-15,k0-7),
                    // r2=(rows0-7,k8-15), r3=(rows8-15,k8-15)
                    // -> n8-tile0 pair {r0,r2}, n8-tile1 pair {r1,r3}
                    mma16816(acc[i][2 * j],     aH + 4 * i, bH[4 * j],     bH[4 * j + 2]);
                    mma16816(acc[i][2 * j + 1], aH + 4 * i, bH[4 * j + 1], bH[4 * j + 3]);
                    mma16816(acc[i][2 * j],     aH + 4 * i, bL[4 * j],     bL[4 * j + 2]);
                    mma16816(acc[i][2 * j + 1], aH + 4 * i, bL[4 * j + 1], bL[4 * j + 3]);
                    mma16816(acc[i][2 * j],     aL + 4 * i, bH[4 * j],     bH[4 * j + 2]);
                    mma16816(acc[i][2 * j + 1], aL + 4 * i, bH[4 * j + 1], bH[4 * j + 3]);
                }
            }
        }

        if (ch + 2 < NCHUNK)
            load_chunk(tiles, (ch + 2) % NSTAGE, Ah, Al, Bh, Bl,
                       (ch + 2) * BK, tid);
    }

    // Epilogue: d-frag layout — d0,d1 at (row = lane/4, col = 2*(lane%4)),
    // d2,d3 at row+8.
    const int er = lane >> 2;
    const int ec = (lane & 3) * 2;
#pragma unroll
    for (int i = 0; i < 4; i++) {
#pragma unroll
        for (int jj = 0; jj < 4; jj++) {
            const int row = m0 + wm + i * 16 + er;
            const int col = n0 + wn + jj * 8 + ec;
            float2 v0 = make_float2(acc[i][jj][0], acc[i][jj][1]);
            float2 v1 = make_float2(acc[i][jj][2], acc[i][jj][3]);
            *(float2*)(C + (size_t)row * DO + col)       = v0;
            *(float2*)(C + (size_t)(row + 8) * DO + col) = v1;
        }
    }
}

// ---------------------------------------------------------------------------
extern "C" void kernel_launch(void* const* d_in, const int* in_sizes, int n_in,
                              void* d_out, int out_size) {
    (void)in_sizes; (void)n_in; (void)out_size;
    const float* x    = (const float*)d_in[0];   // (B, T, DI)
    const float* filt = (const float*)d_in[1];   // (T, NF)
    const float* Mw   = (const float*)d_in[2];   // (NF, DO, DI)
    float*       out  = (float*)d_out;           // (B, T, DO)

    cudaFuncSetAttribute(gemm_kernel,
                         cudaFuncAttributeMaxDynamicSharedMemorySize, SMEM_TOTAL);

    convert_w_kernel<<<(NF * DO * DI) / 256, 256>>>(Mw);
    scan_kernel<<<dim3(NF, B_, DI / 128), 128>>>(x, filt);
    gemm_kernel<<<dim3(DO / BN, MROWS / BM), 256, SMEM_TOTAL>>>(out);
}